// round 3
// baseline (speedup 1.0000x reference)
#include <cuda_runtime.h>

#define NTOK 16384
#define MD   2048
#define PD   256
#define NE   64
#define TOKT 64
#define KB   16
#define NIT  (MD / KB)

// smem layout (floats):
//  Xs   : 2*KB*64   = 2048
//  Ws   : 2*KB*256  = 8192
//  hs   : 64*260    = 16640
//  stage: 8*64      = 512
#define XS_OFF    0
#define WS_OFF    (2*KB*64)
#define HS_OFF    (WS_OFF + 2*KB*256)
#define STAGE_OFF (HS_OFF + 64*260)
#define SMEM_FLOATS (STAGE_OFF + 8*64)
#define SMEM_BYTES  (SMEM_FLOATS * 4)

typedef unsigned long long ull;

__device__ float g_simn[PD * NE];

__device__ __forceinline__ ull pack2(float lo, float hi) {
    ull r; asm("mov.b64 %0, {%1,%2};" : "=l"(r) : "f"(lo), "f"(hi)); return r;
}
__device__ __forceinline__ void unpack2(ull v, float& lo, float& hi) {
    asm("mov.b64 {%0,%1}, %2;" : "=f"(lo), "=f"(hi) : "l"(v));
}
__device__ __forceinline__ void ffma2(ull& d, ull a, ull b) {
    asm("fma.rn.f32x2 %0, %1, %2, %0;" : "+l"(d) : "l"(a), "l"(b));
}

// Normalize each column (dim 0) of sim [256, 64] -> g_simn
__global__ void sim_norm_kernel(const float* __restrict__ sim) {
    __shared__ float part[256];
    __shared__ float inv[64];
    int t = threadIdx.x;
    int c = t & 63;
    int q = t >> 6;           // quarter 0..3
    float ss = 0.0f;
    for (int p = q * 64; p < q * 64 + 64; ++p) {
        float v = sim[p * NE + c];
        ss += v * v;
    }
    part[t] = ss;
    __syncthreads();
    if (q == 0) {
        float tot = part[c] + part[c + 64] + part[c + 128] + part[c + 192];
        inv[c] = 1.0f / fmaxf(sqrtf(tot), 1e-12f);
    }
    __syncthreads();
    float iv = inv[c];
    for (int p = q * 64; p < q * 64 + 64; ++p)
        g_simn[p * NE + c] = sim[p * NE + c] * iv;
}

__global__ __launch_bounds__(256, 1)
void gate_kernel(const float* __restrict__ x,
                 const float* __restrict__ W,
                 const float* __restrict__ bias,
                 const float* __restrict__ temp,
                 const float* __restrict__ mask,
                 float* __restrict__ out,
                 int write_topk)
{
    extern __shared__ float smem[];
    float* Xs    = smem + XS_OFF;
    float* Wsm   = smem + WS_OFF;
    float* hs    = smem + HS_OFF;
    float* stage = smem + STAGE_OFF;

    const int tid = threadIdx.x;
    const int ty  = tid >> 5;   // warp 0..7
    const int tx  = tid & 31;   // lane
    const int tokBase = blockIdx.x * TOKT;

    // ---------------- GEMM1: h[64][256] = x_tile @ W^T ----------------
    // load mapping: x tile: thread -> row = tid/4, kgroup = tid%4 (float4)
    //               W tile: thread -> col = tid, 4 float4 along K
    const int xrow = tid >> 2;
    const int xkg  = (tid & 3);
    const float* xg = x + (size_t)(tokBase + xrow) * MD + xkg * 4;
    const float* wg = W + (size_t)tid * MD;

    float4 rx, rw0, rw1, rw2, rw3;
    rx  = *(const float4*)(xg);
    rw0 = *(const float4*)(wg + 0);
    rw1 = *(const float4*)(wg + 4);
    rw2 = *(const float4*)(wg + 8);
    rw3 = *(const float4*)(wg + 12);

    ull acc[8][4];
    #pragma unroll
    for (int i = 0; i < 8; ++i)
        #pragma unroll
        for (int p = 0; p < 4; ++p) acc[i][p] = 0ull;

    // store tile 0
    {
        float* xs = Xs;
        float* ws = Wsm;
        xs[(xkg * 4 + 0) * 64 + xrow] = rx.x;
        xs[(xkg * 4 + 1) * 64 + xrow] = rx.y;
        xs[(xkg * 4 + 2) * 64 + xrow] = rx.z;
        xs[(xkg * 4 + 3) * 64 + xrow] = rx.w;
        ws[ 0 * 256 + tid] = rw0.x; ws[ 1 * 256 + tid] = rw0.y;
        ws[ 2 * 256 + tid] = rw0.z; ws[ 3 * 256 + tid] = rw0.w;
        ws[ 4 * 256 + tid] = rw1.x; ws[ 5 * 256 + tid] = rw1.y;
        ws[ 6 * 256 + tid] = rw1.z; ws[ 7 * 256 + tid] = rw1.w;
        ws[ 8 * 256 + tid] = rw2.x; ws[ 9 * 256 + tid] = rw2.y;
        ws[10 * 256 + tid] = rw2.z; ws[11 * 256 + tid] = rw2.w;
        ws[12 * 256 + tid] = rw3.x; ws[13 * 256 + tid] = rw3.y;
        ws[14 * 256 + tid] = rw3.z; ws[15 * 256 + tid] = rw3.w;
    }
    __syncthreads();

    int cur = 0;
    for (int it = 0; it < NIT; ++it) {
        const int kbn = (it + 1) * KB;
        if (it + 1 < NIT) {
            rx  = *(const float4*)(xg + kbn);
            rw0 = *(const float4*)(wg + kbn + 0);
            rw1 = *(const float4*)(wg + kbn + 4);
            rw2 = *(const float4*)(wg + kbn + 8);
            rw3 = *(const float4*)(wg + kbn + 12);
        }
        // compute on buffer `cur`
        {
            const float* xs = Xs  + cur * (KB * 64);
            const float* ws = Wsm + cur * (KB * 256);
            #pragma unroll
            for (int k = 0; k < KB; ++k) {
                float4 a0 = *(const float4*)&xs[k * 64 + ty * 8];
                float4 a1 = *(const float4*)&xs[k * 64 + ty * 8 + 4];
                ull aa[8];
                aa[0] = pack2(a0.x, a0.x); aa[1] = pack2(a0.y, a0.y);
                aa[2] = pack2(a0.z, a0.z); aa[3] = pack2(a0.w, a0.w);
                aa[4] = pack2(a1.x, a1.x); aa[5] = pack2(a1.y, a1.y);
                aa[6] = pack2(a1.z, a1.z); aa[7] = pack2(a1.w, a1.w);
                ull bb[4];
                #pragma unroll
                for (int p = 0; p < 4; ++p)
                    bb[p] = *(const ull*)&ws[k * 256 + p * 64 + tx * 2];
                #pragma unroll
                for (int i = 0; i < 8; ++i)
                    #pragma unroll
                    for (int p = 0; p < 4; ++p)
                        ffma2(acc[i][p], aa[i], bb[p]);
            }
        }
        if (it + 1 < NIT) {
            float* xs = Xs  + (cur ^ 1) * (KB * 64);
            float* ws = Wsm + (cur ^ 1) * (KB * 256);
            xs[(xkg * 4 + 0) * 64 + xrow] = rx.x;
            xs[(xkg * 4 + 1) * 64 + xrow] = rx.y;
            xs[(xkg * 4 + 2) * 64 + xrow] = rx.z;
            xs[(xkg * 4 + 3) * 64 + xrow] = rx.w;
            ws[ 0 * 256 + tid] = rw0.x; ws[ 1 * 256 + tid] = rw0.y;
            ws[ 2 * 256 + tid] = rw0.z; ws[ 3 * 256 + tid] = rw0.w;
            ws[ 4 * 256 + tid] = rw1.x; ws[ 5 * 256 + tid] = rw1.y;
            ws[ 6 * 256 + tid] = rw1.z; ws[ 7 * 256 + tid] = rw1.w;
            ws[ 8 * 256 + tid] = rw2.x; ws[ 9 * 256 + tid] = rw2.y;
            ws[10 * 256 + tid] = rw2.z; ws[11 * 256 + tid] = rw2.w;
            ws[12 * 256 + tid] = rw3.x; ws[13 * 256 + tid] = rw3.y;
            ws[14 * 256 + tid] = rw3.z; ws[15 * 256 + tid] = rw3.w;
        }
        __syncthreads();
        cur ^= 1;
    }

    // ---------------- bias + row L2-norm + store h to smem ----------------
    // warp ty owns rows ty*8 .. ty*8+7 fully (cols spread over lanes)
    float bl[4], bh[4];
    #pragma unroll
    for (int p = 0; p < 4; ++p) {
        bl[p] = bias[p * 64 + tx * 2];
        bh[p] = bias[p * 64 + tx * 2 + 1];
    }
    #pragma unroll
    for (int i = 0; i < 8; ++i) {
        float v[8];
        #pragma unroll
        for (int p = 0; p < 4; ++p) {
            float lo, hi;
            unpack2(acc[i][p], lo, hi);
            v[2 * p]     = lo + bl[p];
            v[2 * p + 1] = hi + bh[p];
        }
        float ss = 0.0f;
        #pragma unroll
        for (int j = 0; j < 8; ++j) ss += v[j] * v[j];
        #pragma unroll
        for (int o = 16; o > 0; o >>= 1)
            ss += __shfl_xor_sync(0xffffffffu, ss, o);
        float inv = 1.0f / fmaxf(sqrtf(ss), 1e-12f);
        int row = ty * 8 + i;
        #pragma unroll
        for (int p = 0; p < 4; ++p) {
            float2 hv;
            hv.x = v[2 * p] * inv;
            hv.y = v[2 * p + 1] * inv;
            *(float2*)&hs[row * 260 + p * 64 + tx * 2] = hv;
        }
    }
    __syncwarp();

    // ---------------- GEMM2: logits[8 tokens][64 experts] per warp --------
    // lane tx computes experts tx and tx+32 for tokens ty*8 .. ty*8+7
    // sim_norm read straight from global (64KB, L1/L2 resident, coalesced).
    float l0[8], l1[8];
    #pragma unroll
    for (int t = 0; t < 8; ++t) { l0[t] = 0.0f; l1[t] = 0.0f; }
    const int rowb = ty * 8;
    #pragma unroll 4
    for (int p = 0; p < PD; ++p) {
        float s0 = __ldg(&g_simn[p * 64 + tx]);
        float s1 = __ldg(&g_simn[p * 64 + tx + 32]);
        #pragma unroll
        for (int t = 0; t < 8; ++t) {
            float hv = hs[(rowb + t) * 260 + p];
            l0[t] = fmaf(hv, s0, l0[t]);
            l1[t] = fmaf(hv, s1, l1[t]);
        }
    }

    // ---------------- scale, mask, softmax, threshold top-k ---------------
    const float scale = expf(fminf(temp[0], 4.60517018598809136804f));
    const float m0 = mask[tx];
    const float m1 = mask[tx + 32];
    const unsigned full = 0xffffffffu;
    const int active = __popc(__ballot_sync(full, m0 != 0.0f)) +
                       __popc(__ballot_sync(full, m1 != 0.0f));
    float* st = stage + ty * 64;

    #pragma unroll
    for (int t = 0; t < 8; ++t) {
        const int tok = tokBase + rowb + t;
        float L0 = (m0 == 0.0f) ? -1e9f : l0[t] * scale;
        float L1 = (m1 == 0.0f) ? -1e9f : l1[t] * scale;
        out[(size_t)tok * NE + tx]      = L0;
        out[(size_t)tok * NE + tx + 32] = L1;

        float mx = fmaxf(L0, L1);
        #pragma unroll
        for (int o = 16; o > 0; o >>= 1)
            mx = fmaxf(mx, __shfl_xor_sync(full, mx, o));
        float e0 = expf(L0 - mx);
        float e1 = expf(L1 - mx);
        float sum = e0 + e1;
        #pragma unroll
        for (int o = 16; o > 0; o >>= 1)
            sum += __shfl_xor_sync(full, sum, o);
        float r = 1.0f / sum;
        float sc0 = e0 * r + 1e-14f;
        float sc1 = e1 * r + 1e-14f;

        st[tx]      = sc0;
        st[tx + 32] = sc1;
        __syncwarp();

        // exclusive-prefix-in-sorted-order = sum of strictly greater scores
        // + sum of equal scores with smaller original index (stable desc sort)
        float g0 = 0.0f, g1 = 0.0f;
        #pragma unroll 8
        for (int f = 0; f < 64; ++f) {
            float sf = st[f];
            if (sf > sc0 || (sf == sc0 && f < tx))      g0 += sf;
            if (sf > sc1 || (sf == sc1 && f < tx + 32)) g1 += sf;
        }
        int cnt = __popc(__ballot_sync(full, g0 < 1.0f)) +
                  __popc(__ballot_sync(full, g1 < 1.0f));
        int tk = cnt < active ? cnt : active;
        if (write_topk && tx == 0)
            out[(size_t)NTOK * NE + tok] = (float)tk;
        __syncwarp();
    }
}

extern "C" void kernel_launch(void* const* d_in, const int* in_sizes, int n_in,
                              void* d_out, int out_size)
{
    const float* x    = (const float*)d_in[0];
    const float* W    = (const float*)d_in[1];
    const float* b    = (const float*)d_in[2];
    const float* sim  = (const float*)d_in[3];
    const float* temp = (const float*)d_in[4];
    const float* mask = (const float*)d_in[5];
    float* out = (float*)d_out;

    cudaFuncSetAttribute(gate_kernel,
                         cudaFuncAttributeMaxDynamicSharedMemorySize,
                         SMEM_BYTES);

    sim_norm_kernel<<<1, 256>>>(sim);

    const int write_topk = (out_size >= NTOK * NE + NTOK) ? 1 : 0;
    gate_kernel<<<NTOK / TOKT, 256, SMEM_BYTES>>>(x, W, b, temp, mask, out,
                                                  write_topk);
}